// round 14
// baseline (speedup 1.0000x reference)
#include <cuda_runtime.h>
#include <math.h>
#include <stdint.h>

#define Cc  384
#define DIc 768
#define Sd  256
#define Rr  24
#define Kc  4
#define Bb  2
#define Ll  512
#define BL  (Bb*Ll)          // 1024
#define XD  (Rr + 2*Sd)      // 536
#define NCH 8
#define LCH 64

typedef unsigned long long ull;

// ---------------- f32x2 packed helpers ----------------
__device__ __forceinline__ ull fma2(ull a, ull b, ull c) {
    ull d;
    asm("fma.rn.f32x2 %0, %1, %2, %3;" : "=l"(d) : "l"(a), "l"(b), "l"(c));
    return d;
}
__device__ __forceinline__ ull mul2(ull a, ull b) {
    ull d;
    asm("mul.rn.f32x2 %0, %1, %2;" : "=l"(d) : "l"(a), "l"(b));
    return d;
}
__device__ __forceinline__ ull pack2(float x, float y) {
    ull d;
    asm("mov.b64 %0, {%1, %2};" : "=l"(d) : "f"(x), "f"(y));
    return d;
}
__device__ __forceinline__ float2 unpack2(ull v) {
    float2 r;
    asm("mov.b64 {%0, %1}, %2;" : "=f"(r.x), "=f"(r.y) : "l"(v));
    return r;
}

__device__ __forceinline__ void cpa16(uint32_t dst, const void* src) {
    asm volatile("cp.async.ca.shared.global [%0], [%1], 16;" :: "r"(dst), "l"(src));
}
__device__ __forceinline__ uint32_t f2tf(float f) {
    uint32_t r;
    asm("cvt.rna.tf32.f32 %0, %1;" : "=r"(r) : "f"(f));
    return r;
}
__device__ __forceinline__ float rndtf(float f) { return __uint_as_float(f2tf(f)); }

__device__ __forceinline__ void mma8(float* c, const uint32_t* a, const uint32_t* b) {
    asm volatile(
        "mma.sync.aligned.m16n8k8.row.col.f32.tf32.tf32.f32 "
        "{%0,%1,%2,%3}, {%4,%5,%6,%7}, {%8,%9}, {%0,%1,%2,%3};"
        : "+f"(c[0]), "+f"(c[1]), "+f"(c[2]), "+f"(c[3])
        : "r"(a[0]), "r"(a[1]), "r"(a[2]), "r"(a[3]), "r"(b[0]), "r"(b[1]));
}

// ---------------- scratch ----------------
__device__ __align__(16) float g_u[BL*Cc];     // fp32 ln1 output (for tgemm3)
__device__ __align__(16) float g_uh[BL*Cc];    // tf32-rounded ln1 output (for z GEMM)
__device__ __align__(16) float g_wz [DIc*Cc];
__device__ __align__(16) float g_wxp[XD*DIc];
__device__ __align__(16) float g_wop[Cc*DIc];
__device__ __align__(16) float g_whd[Cc*Cc];
__device__ __align__(16) float g_xz[BL*2*DIc];
__device__ __align__(16) float g_xact[BL*DIc];
__device__ __align__(16) float g_xactr[BL*DIc];
__device__ __align__(16) float g_xdbl[BL*XD];
__device__ __align__(16) float g_dt[BL*DIc];
__device__ __align__(16) float g_e[BL*DIc];
__device__ __align__(16) float g_du[BL*DIc];
__device__ __align__(16) float g_A[DIc*Sd];
__device__ int   g_powA = 1;
__device__ __align__(16) float g_y[BL*DIc];
__device__ __align__(16) float g_res1[BL*Cc];
__device__ __align__(16) float g_t2[BL*Cc];
__device__ __align__(16) float g_part[4*BL*XD];
__device__ __align__(16) float g_hend[Bb*NCH*DIc*Sd];
__device__ __align__(16) float g_hin [Bb*NCH*DIc*Sd];

// ---------------- ln1: fp32 + tf32-rounded outputs ----------------
__global__ __launch_bounds__(128) void ln1_kernel(const float* __restrict__ x,
                                                  const float* __restrict__ gw,
                                                  const float* __restrict__ bw,
                                                  float* __restrict__ u_out,
                                                  float* __restrict__ uh_out) {
    int row = blockIdx.x;
    const float* xr = x + (size_t)row * Cc;
    float v[3];
#pragma unroll
    for (int i = 0; i < 3; i++) v[i] = xr[threadIdx.x + i*128];
    float s = v[0]+v[1]+v[2];
    float q = v[0]*v[0]+v[1]*v[1]+v[2]*v[2];
#pragma unroll
    for (int o = 16; o; o >>= 1) {
        s += __shfl_xor_sync(0xffffffffu, s, o);
        q += __shfl_xor_sync(0xffffffffu, q, o);
    }
    __shared__ float sh[8];
    int wid = threadIdx.x >> 5, ln = threadIdx.x & 31;
    if (ln == 0) { sh[wid] = s; sh[wid+4] = q; }
    __syncthreads();
    s = sh[0]+sh[1]+sh[2]+sh[3];
    q = sh[4]+sh[5]+sh[6]+sh[7];
    float mu  = s * (1.f/Cc);
    float var = q * (1.f/Cc) - mu*mu;
    float rs  = rsqrtf(var + 1e-5f);
#pragma unroll
    for (int i = 0; i < 3; i++) {
        int c = threadIdx.x + i*128;
        float o = (v[i]-mu)*rs*gw[c] + bw[c];
        u_out[(size_t)row*Cc + c]  = o;
        uh_out[(size_t)row*Cc + c] = rndtf(o);
    }
}

// ------------- ln2 fused with 4-partial add; t2 rounded to tf32 -----------------
__global__ __launch_bounds__(128) void ln_add_kernel(const float* __restrict__ qp,
                                                     const float* __restrict__ xr0,
                                                     const float* __restrict__ gw,
                                                     const float* __restrict__ bw,
                                                     float* __restrict__ res_out,
                                                     float* __restrict__ out) {
    int row = blockIdx.x;
    size_t base = (size_t)row * Cc;
    const size_t S = (size_t)BL*Cc;
    float v[3];
#pragma unroll
    for (int i = 0; i < 3; i++) {
        size_t c = base + threadIdx.x + i*128;
        v[i] = (qp[c] + qp[S+c]) + (qp[2*S+c] + qp[3*S+c]) + xr0[c];
        res_out[c] = v[i];
    }
    float s = v[0]+v[1]+v[2];
    float q = v[0]*v[0]+v[1]*v[1]+v[2]*v[2];
#pragma unroll
    for (int o = 16; o; o >>= 1) {
        s += __shfl_xor_sync(0xffffffffu, s, o);
        q += __shfl_xor_sync(0xffffffffu, q, o);
    }
    __shared__ float sh[8];
    int wid = threadIdx.x >> 5, ln = threadIdx.x & 31;
    if (ln == 0) { sh[wid] = s; sh[wid+4] = q; }
    __syncthreads();
    s = sh[0]+sh[1]+sh[2]+sh[3];
    q = sh[4]+sh[5]+sh[6]+sh[7];
    float mu  = s * (1.f/Cc);
    float var = q * (1.f/Cc) - mu*mu;
    float rs  = rsqrtf(var + 1e-5f);
#pragma unroll
    for (int i = 0; i < 3; i++) {
        int c = threadIdx.x + i*128;
        out[base + c] = rndtf((v[i]-mu)*rs*gw[c] + bw[c]);
    }
}

// ------------ 1x tf32 GEMM: 128x64 tile, 256 thr, split-K via gridDim.z ---------
// Operands must be pre-rounded to tf32 (rna); raw-feed is then exact.
#define GP 36
#define ABUF (128*GP)
#define WBUF (64*GP)
#define TG_SMEM ((2*(ABUF+WBUF))*4)   // 55296

__device__ __forceinline__ void tg_stage(const float* __restrict__ A,
                                         const float* __restrict__ W,
                                         int N, int kp, int m0, int n0, int i, int kOff,
                                         uint32_t Au, uint32_t Wu, int tid) {
    int k0 = kOff + (i << 5);
#pragma unroll
    for (int j = 0; j < 4; j++) {
        int idx = tid + j*256;
        int r = idx >> 3, c = idx & 7;
        cpa16(Au + (unsigned)(r*GP + c*4)*4, A + (size_t)(m0+r)*kp + k0 + c*4);
    }
#pragma unroll
    for (int j = 0; j < 2; j++) {
        int idx = tid + j*256;
        int r = idx >> 3, c = idx & 7;
        uint32_t dst = Wu + (unsigned)(r*GP + c*4)*4;
        int gn = n0 + r;
        if (gn < N)
            cpa16(dst, W + (size_t)gn*kp + k0 + c*4);
        else
            asm volatile("st.shared.v4.b32 [%0], {%1,%1,%1,%1};" :: "r"(dst), "r"(0u) : "memory");
    }
    asm volatile("cp.async.commit_group;" ::: "memory");
}

__global__ __launch_bounds__(256) void tgemm(const float* __restrict__ A,
                                             const float* __restrict__ W,
                                             float* __restrict__ out,
                                             int M, int N, int kLen, int kp,
                                             int ldo, size_t pStride) {
    extern __shared__ float sm[];
    uint32_t sb;
    asm("{ .reg .u64 t; cvta.to.shared.u64 t, %1; cvt.u32.u64 %0, t; }" : "=r"(sb) : "l"(sm));
    const int tid = threadIdx.x, lane = tid & 31, wid = tid >> 5;
    const int wm = wid & 3, wn = wid >> 2;
    const int m0 = blockIdx.y * 128, n0 = blockIdx.x * 64;
    const int kOff = blockIdx.z * kLen;
    const int nch = kLen >> 5;
    out += (size_t)blockIdx.z * pStride;

    float* Ab[2] = { sm,        sm + ABUF + WBUF };
    float* Wb[2] = { sm + ABUF, sm + 2*ABUF + WBUF };
    uint32_t Au[2] = { sb,          sb + (ABUF + WBUF)*4 };
    uint32_t Wu[2] = { sb + ABUF*4, sb + (2*ABUF + WBUF)*4 };

    float acc[2][4][4] = {};

    tg_stage(A, W, N, kp, m0, n0, 0, kOff, Au[0], Wu[0], tid);
    if (nch > 1) tg_stage(A, W, N, kp, m0, n0, 1, kOff, Au[1], Wu[1], tid);

    const int lq = lane >> 2, lr = lane & 3;

    for (int i = 0; i < nch; i++) {
        int buf = i & 1;
        if (i + 1 < nch) asm volatile("cp.async.wait_group 1;" ::: "memory");
        else             asm volatile("cp.async.wait_group 0;" ::: "memory");
        __syncthreads();
        const float* Ap = Ab[buf];
        const float* Wp = Wb[buf];
#pragma unroll
        for (int k8 = 0; k8 < 4; k8++) {
            int kb = k8*8 + lr;
            uint32_t ah[2][4];
#pragma unroll
            for (int t = 0; t < 2; t++) {
                int rb = wm*32 + t*16 + lq;
                ah[t][0] = __float_as_uint(Ap[rb*GP + kb]);
                ah[t][1] = __float_as_uint(Ap[(rb+8)*GP + kb]);
                ah[t][2] = __float_as_uint(Ap[rb*GP + kb + 4]);
                ah[t][3] = __float_as_uint(Ap[(rb+8)*GP + kb + 4]);
            }
            uint32_t bh[4][2];
#pragma unroll
            for (int j = 0; j < 4; j++) {
                int nb = wn*32 + j*8 + lq;
                bh[j][0] = __float_as_uint(Wp[nb*GP + kb]);
                bh[j][1] = __float_as_uint(Wp[nb*GP + kb + 4]);
            }
#pragma unroll
            for (int t = 0; t < 2; t++)
#pragma unroll
                for (int j = 0; j < 4; j++)
                    mma8(acc[t][j], ah[t], bh[j]);
        }
        if (i + 2 < nch) {
            __syncthreads();
            tg_stage(A, W, N, kp, m0, n0, i + 2, kOff, Au[buf], Wu[buf], tid);
        }
    }

#pragma unroll
    for (int t = 0; t < 2; t++) {
        int r0 = m0 + wm*32 + t*16 + lq;
#pragma unroll
        for (int j = 0; j < 4; j++) {
            int gn = n0 + wn*32 + j*8 + lr*2;
            if (gn >= N) continue;
            const float* c = acc[t][j];
            float* p0 = out + (size_t)r0 * ldo + gn;
            float* p1 = out + (size_t)(r0+8) * ldo + gn;
            p0[0] = c[0]; p0[1] = c[1];
            p1[0] = c[2]; p1[1] = c[3];
        }
    }
}

// ------- 3x tf32 GEMM (in-loop cvt split), 128x64 tile, K-chunk 16, split-K -----
#define GP3 20
#define A3 (128*GP3)
#define W3 (64*GP3)
#define T3_SMEM ((2*(A3+W3))*4)   // 30720

__device__ __forceinline__ void t3_stage(const float* __restrict__ A,
                                         const float* __restrict__ W,
                                         int kp, int m0, int n0, int i, int kOff,
                                         uint32_t Au, uint32_t Wu, int tid) {
    int k0 = kOff + (i << 4);
#pragma unroll
    for (int j = 0; j < 2; j++) {
        int idx = tid + j*256;
        int r = idx >> 2, c = idx & 3;
        cpa16(Au + (unsigned)(r*GP3 + c*4)*4, A + (size_t)(m0+r)*kp + k0 + c*4);
    }
    {
        int r = tid >> 2, c = tid & 3;
        cpa16(Wu + (unsigned)(r*GP3 + c*4)*4, W + (size_t)(n0+r)*kp + k0 + c*4);
    }
    asm volatile("cp.async.commit_group;" ::: "memory");
}

__global__ __launch_bounds__(256) void tgemm3(const float* __restrict__ A,
                                              const float* __restrict__ W,
                                              float* __restrict__ out,
                                              int kLen, int kp, int ldo, size_t pStride) {
    extern __shared__ float sm[];
    uint32_t sb;
    asm("{ .reg .u64 t; cvta.to.shared.u64 t, %1; cvt.u32.u64 %0, t; }" : "=r"(sb) : "l"(sm));
    const int tid = threadIdx.x, lane = tid & 31, wid = tid >> 5;
    const int wm = wid & 3, wn = wid >> 2;
    const int m0 = blockIdx.y * 128, n0 = blockIdx.x * 64;
    const int kOff = blockIdx.z * kLen;
    const int nch = kLen >> 4;
    out += (size_t)blockIdx.z * pStride;

    float* Ab[2] = { sm,      sm + A3 + W3 };
    float* Wb[2] = { sm + A3, sm + 2*A3 + W3 };
    uint32_t Au[2] = { sb,         sb + (A3 + W3)*4 };
    uint32_t Wu[2] = { sb + A3*4,  sb + (2*A3 + W3)*4 };

    float acc[2][4][4] = {};

    t3_stage(A, W, kp, m0, n0, 0, kOff, Au[0], Wu[0], tid);
    if (nch > 1) t3_stage(A, W, kp, m0, n0, 1, kOff, Au[1], Wu[1], tid);

    const int lq = lane >> 2, lr = lane & 3;

    for (int i = 0; i < nch; i++) {
        int buf = i & 1;
        if (i + 1 < nch) asm volatile("cp.async.wait_group 1;" ::: "memory");
        else             asm volatile("cp.async.wait_group 0;" ::: "memory");
        __syncthreads();
        const float* Ap = Ab[buf];
        const float* Wp = Wb[buf];
#pragma unroll
        for (int k8 = 0; k8 < 2; k8++) {
            int kb = k8*8 + lr;
            uint32_t ah[2][4], al[2][4];
#pragma unroll
            for (int t = 0; t < 2; t++) {
                int rb = wm*32 + t*16 + lq;
                float v0 = Ap[rb*GP3 + kb];
                float v1 = Ap[(rb+8)*GP3 + kb];
                float v2 = Ap[rb*GP3 + kb + 4];
                float v3 = Ap[(rb+8)*GP3 + kb + 4];
                ah[t][0] = f2tf(v0); ah[t][1] = f2tf(v1);
                ah[t][2] = f2tf(v2); ah[t][3] = f2tf(v3);
                al[t][0] = f2tf(v0 - __uint_as_float(ah[t][0]));
                al[t][1] = f2tf(v1 - __uint_as_float(ah[t][1]));
                al[t][2] = f2tf(v2 - __uint_as_float(ah[t][2]));
                al[t][3] = f2tf(v3 - __uint_as_float(ah[t][3]));
            }
            uint32_t bh[4][2], bl[4][2];
#pragma unroll
            for (int j = 0; j < 4; j++) {
                int nb = wn*32 + j*8 + lq;
                float v0 = Wp[nb*GP3 + kb];
                float v1 = Wp[nb*GP3 + kb + 4];
                bh[j][0] = f2tf(v0); bh[j][1] = f2tf(v1);
                bl[j][0] = f2tf(v0 - __uint_as_float(bh[j][0]));
                bl[j][1] = f2tf(v1 - __uint_as_float(bh[j][1]));
            }
#pragma unroll
            for (int t = 0; t < 2; t++)
#pragma unroll
                for (int j = 0; j < 4; j++) {
                    mma8(acc[t][j], ah[t], bh[j]);
                    mma8(acc[t][j], ah[t], bl[j]);
                    mma8(acc[t][j], al[t], bh[j]);
                }
        }
        if (i + 2 < nch) {
            __syncthreads();
            t3_stage(A, W, kp, m0, n0, i + 2, kOff, Au[buf], Wu[buf], tid);
        }
    }

#pragma unroll
    for (int t = 0; t < 2; t++) {
        int r0 = m0 + wm*32 + t*16 + lq;
#pragma unroll
        for (int j = 0; j < 4; j++) {
            int gn = n0 + wn*32 + j*8 + lr*2;
            const float* c = acc[t][j];
            float* p0 = out + (size_t)r0 * ldo + gn;
            float* p1 = out + (size_t)(r0+8) * ldo + gn;
            p0[0] = c[0]; p0[1] = c[1];
            p1[0] = c[2]; p1[1] = c[3];
        }
    }
}

// ---------------- elementwise adds ----------------
__global__ void addin_kernel() {   // sum 3 tgemm3 partials -> g_xz x-half
    int i = blockIdx.x*256 + threadIdx.x;
    if (i >= BL*DIc) return;
    const size_t S = (size_t)BL*DIc;
    int row = i / DIc, col = i - row*DIc;
    g_xz[(size_t)row*(2*DIc) + col] = g_part[i] + g_part[S+i] + g_part[2*S+i];
}
__global__ void addx_kernel() {
    int i = blockIdx.x*256 + threadIdx.x;
    if (i >= BL*XD) return;
    const size_t S = (size_t)BL*XD;
    g_xdbl[i] = (g_part[i] + g_part[S+i]) + (g_part[2*S+i] + g_part[3*S+i]);
}
__global__ void addh_kernel(const float* __restrict__ hb, float* __restrict__ out) {
    int i = blockIdx.x*256 + threadIdx.x;
    if (i >= BL*Cc) return;
    const size_t S = (size_t)BL*Cc;
    int col = i - (i/Cc)*Cc;
    out[i] = (g_part[i] + g_part[S+i]) + (g_part[2*S+i] + g_part[3*S+i])
           + g_res1[i] + hb[col];
}

// ---------------- causal depthwise conv (K=4) + SiLU; rounded copy --------------
__global__ void conv_kernel(const float* __restrict__ cw, const float* __restrict__ cb) {
    int i = blockIdx.x * blockDim.x + threadIdx.x;
    if (i >= BL*DIc) return;
    int d  = i % DIc;
    int bl = i / DIc;
    int l  = bl % Ll;
    int b  = bl / Ll;
    float acc = cb[d];
#pragma unroll
    for (int k = 0; k < Kc; ++k) {
        int ls = l - (Kc-1) + k;
        if (ls >= 0)
            acc += cw[d*Kc + k] * g_xz[(size_t)(b*Ll + ls)*(2*DIc) + d];
    }
    float sg = 1.f/(1.f + __expf(-acc));
    float xa = acc * sg;
    g_xact[i]  = xa;
    g_xactr[i] = rndtf(xa);
}

// ---------- dt: exact fp32 x_proj dt-slice + dt_proj + softplus + exp/du --------
__global__ __launch_bounds__(192) void dt_kernel(const float* __restrict__ Wx,
                                                 const float* __restrict__ Wdt,
                                                 const float* __restrict__ bdt) {
    __shared__ float sx[DIc];
    __shared__ float sdt[Rr];
    int row = blockIdx.x, tid = threadIdx.x;
    const float* xr = g_xact + (size_t)row * DIc;
    for (int i = tid; i < DIc; i += 192) sx[i] = xr[i];
    __syncthreads();
    int r = tid >> 3, sl = tid & 7;
    const float* wrow = Wx + (size_t)r * DIc;
    float acc = 0.f;
    for (int k = sl; k < DIc; k += 8) acc += sx[k] * wrow[k];
    acc += __shfl_xor_sync(0xffffffffu, acc, 4);
    acc += __shfl_xor_sync(0xffffffffu, acc, 2);
    acc += __shfl_xor_sync(0xffffffffu, acc, 1);
    if (sl == 0) sdt[r] = acc;
    __syncthreads();
    for (int d = tid; d < DIc; d += 192) {
        float a = bdt[d];
#pragma unroll
        for (int rr = 0; rr < Rr; rr++) a += sdt[rr] * Wdt[d*Rr + rr];
        float sp = fmaxf(a, 0.f) + log1pf(__expf(-fabsf(a)));
        size_t idx = (size_t)row*DIc + d;
        g_dt[idx] = sp;
        g_e[idx]  = __expf(-sp);
        g_du[idx] = sp * sx[d];
    }
}

// ------- prep: A precompute/check + weight tf32 roundings ----------
__global__ __launch_bounds__(256) void prep_kernel(const float* __restrict__ Alog,
                                                   const float* __restrict__ Win,
                                                   const float* __restrict__ Wxp,
                                                   const float* __restrict__ Wop,
                                                   const float* __restrict__ Whd) {
    int i0 = blockIdx.x*256 + threadIdx.x;
    int stride = gridDim.x*256;
    for (int i = i0; i < DIc*Sd; i += stride) {
        float a = -__expf(Alog[i]);
        g_A[i] = a;
        float tgt = (float)(i % Sd + 1);
        if (fabsf(a + tgt) > 1e-5f * tgt) g_powA = 0;
    }
    for (int i = i0; i < DIc*Cc; i += stride)
        g_wz[i] = rndtf(Win[(size_t)DIc*Cc + i]);
    for (int i = i0; i < XD*DIc; i += stride) g_wxp[i] = rndtf(Wxp[i]);
    for (int i = i0; i < Cc*DIc; i += stride) g_wop[i] = rndtf(Wop[i]);
    for (int i = i0; i < Cc*Cc;  i += stride) g_whd[i] = rndtf(Whd[i]);
}

// ---------------- chunked selective scan ----------------------------------------
struct Chunk { float dt0, dt1, e0, e1, du0, du1, xa0, xa1, z0, z1; };

__device__ __forceinline__ void load_chunk_k1(int b, int tbase, int lane, int ch0, int ch1, Chunk& c) {
    size_t bl = (size_t)b*Ll + tbase + lane;
    size_t i0 = bl*DIc + ch0, i1 = bl*DIc + ch1;
    c.dt0 = g_dt[i0];  c.dt1 = g_dt[i1];
    c.e0  = g_e[i0];   c.e1  = g_e[i1];
    c.du0 = g_du[i0];  c.du1 = g_du[i1];
}
__device__ __forceinline__ void load_chunk_k3(int b, int tbase, int lane, int ch0, int ch1, Chunk& c) {
    size_t bl = (size_t)b*Ll + tbase + lane;
    size_t i0 = bl*DIc + ch0, i1 = bl*DIc + ch1;
    c.dt0 = g_dt[i0];  c.dt1 = g_dt[i1];
    c.e0  = g_e[i0];   c.e1  = g_e[i1];
    c.xa0 = g_xact[i0]; c.xa1 = g_xact[i1];
    c.z0  = g_xz[bl*(2*DIc) + DIc + ch0];
    c.z1  = g_xz[bl*(2*DIc) + DIc + ch1];
}

struct RowU { ull B[4]; ull C[4]; };

__device__ __forceinline__ void step_update(int ti, int slot, const Chunk& ck, const RowU& r,
                                            ull (&H0)[4], ull (&H1)[4],
                                            bool powA, const float (&a0)[8], const float (&a1)[8],
                                            float nS1, float* yb0, float* yb1, int lane) {
    const unsigned m = 0xffffffffu;
    float dt0 = __shfl_sync(m, ck.dt0, ti);
    float dt1 = __shfl_sync(m, ck.dt1, ti);
    float e0  = __shfl_sync(m, ck.e0,  ti);
    float e1  = __shfl_sync(m, ck.e1,  ti);
    float du0 = __shfl_sync(m, ck.du0, ti);
    float du1 = __shfl_sync(m, ck.du1, ti);
    ull P0[4], P1[4];
    if (powA) {
        float p0 = __expf(dt0 * nS1);
        float p1 = __expf(dt1 * nS1);
        ull E0 = pack2(e0*e0, e0*e0);
        ull E1 = pack2(e1*e1, e1*e1);
        P0[0] = pack2(p0, p0*e0);
        P1[0] = pack2(p1, p1*e1);
        P0[1] = mul2(P0[0], E0); P0[2] = mul2(P0[1], E0); P0[3] = mul2(P0[2], E0);
        P1[1] = mul2(P1[0], E1); P1[2] = mul2(P1[1], E1); P1[3] = mul2(P1[2], E1);
    } else {
#pragma unroll
        for (int j = 0; j < 4; j++) {
            P0[j] = pack2(__expf(dt0*a0[2*j]), __expf(dt0*a0[2*j+1]));
            P1[j] = pack2(__expf(dt1*a1[2*j]), __expf(dt1*a1[2*j+1]));
        }
    }
    ull du0p = pack2(du0, du0);
    ull du1p = pack2(du1, du1);
    ull ya0 = 0ull, ya1 = 0ull;
#pragma unroll
    for (int j = 0; j < 4; j++) {
        H0[j] = fma2(P0[j], H0[j], mul2(du0p, r.B[j]));
        ya0   = fma2(H0[j], r.C[j], ya0);
        H1[j] = fma2(P1[j], H1[j], mul2(du1p, r.B[j]));
        ya1   = fma2(H1[j], r.C[j], ya1);
    }
    float2 u0 = unpack2(ya0);
    float2 u1 = unpack2(ya1);
    yb0[lane*17 + slot] = u0.x + u0.y;
    yb1[lane*17 + slot] = u1.x + u1.y;
}

// K1: local scan per chunk.  grid = Bb*NCH*(DIc/8) = 1536 blocks, 128 thr.
__global__ __launch_bounds__(128, 4) void scan1_kernel() {
    __shared__ __align__(16) float ring[3][4*512];
    __shared__ float ybuf[4][2][32*17];
    const int tid  = threadIdx.x;
    const int w    = tid >> 5;
    const int lane = tid & 31;
    const int dg   = blockIdx.x % (DIc/8);
    const int cch  = (blockIdx.x / (DIc/8)) % NCH;
    const int b    = blockIdx.x / (NCH*(DIc/8));
    const int ch0  = dg*8 + w*2, ch1 = ch0 + 1;
    const int s0   = lane*8;
    const int t0   = cch*LCH;
    const float nS1 = -(float)(s0 + 1);
    const float* xd = g_xdbl + (size_t)b*Ll*XD;
    float* yb0 = ybuf[w][0];
    float* yb1 = ybuf[w][1];

    const int off = tid * 4;
    const float* srcbase = (off < 256) ? (xd + Rr + off) : (xd + Rr + Sd + (off - 256));
    unsigned ringaddr[3];
#pragma unroll
    for (int s = 0; s < 3; s++)
        ringaddr[s] = (unsigned)__cvta_generic_to_shared(&ring[s][off]);

    ull H0[4] = {}, H1[4] = {};
    float a0[8], a1[8];
    bool powA = (g_powA != 0);
    if (!powA) {
#pragma unroll
        for (int j = 0; j < 8; j++) {
            a0[j] = g_A[(size_t)ch0*Sd + s0 + j];
            a1[j] = g_A[(size_t)ch1*Sd + s0 + j];
        }
    } else {
#pragma unroll
        for (int j = 0; j < 8; j++) { a0[j] = 0.f; a1[j] = 0.f; }
    }

    Chunk cur, nxt;
    load_chunk_k1(b, t0, lane, ch0, ch1, cur);
    load_chunk_k1(b, t0 + 32, lane, ch0, ch1, nxt);

#pragma unroll
    for (int ss = 0; ss < 2; ss++) {
        const float* sp = srcbase + (size_t)(t0 + ss*4)*XD;
#pragma unroll
        for (int j = 0; j < 4; j++)
            cpa16(ringaddr[ss] + j*2048, sp + (size_t)j*XD);
        asm volatile("cp.async.commit_group;" ::: "memory");
    }

    for (int c2 = 0; c2 < 2; c2++) {
#pragma unroll
        for (int half = 0; half < 2; half++) {
            for (int q = 0; q < 4; q++) {
                int ss = c2*8 + half*4 + q;
                asm volatile("cp.async.wait_group 1;" ::: "memory");
                __syncthreads();
                int slot = ss % 3;
                const float* rb = ring[slot];
#pragma unroll
                for (int j = 0; j < 4; j++) {
                    RowU r;
                    const float* p = rb + j*512;
                    ulonglong2 b01 = *(const ulonglong2*)(p + s0);
                    ulonglong2 b23 = *(const ulonglong2*)(p + s0 + 4);
                    ulonglong2 c01 = *(const ulonglong2*)(p + 256 + s0);
                    ulonglong2 c23 = *(const ulonglong2*)(p + 256 + s0 + 4);
                    r.B[0]=b01.x; r.B[1]=b01.y; r.B[2]=b23.x; r.B[3]=b23.y;
                    r.C[0]=c01.x; r.C[1]=c01.y; r.C[2]=c23.x; r.C[3]=c23.y;
                    int ti = half*16 + q*4 + j;
                    step_update(ti, q*4 + j, cur, r, H0, H1, powA, a0, a1, nS1, yb0, yb1, lane);
                }
                int ns = ss + 2;
                if (ns < 16) {
                    const float* sp = srcbase + (size_t)(t0 + ns*4)*XD;
#pragma unroll
                    for (int j = 0; j < 4; j++)
                        cpa16(ringaddr[ns % 3] + j*2048, sp + (size_t)j*XD);
                }
                asm volatile("cp.async.commit_group;" ::: "memory");
            }
            __syncwarp();
            {
                int t15 = lane & 15;
                int lb  = (lane < 16) ? 0 : 16;
                float acc0 = 0.f, acc1 = 0.f;
#pragma unroll
                for (int l = 0; l < 16; l++) {
                    acc0 += yb0[(lb + l)*17 + t15];
                    acc1 += yb1[(lb + l)*17 + t15];
                }
                acc0 += __shfl_xor_sync(0xffffffffu, acc0, 16);
                acc1 += __shfl_xor_sync(0xffffffffu, acc1, 16);
                bool mine = half ? (lane >= 16) : (lane < 16);
                if (mine) {
                    size_t bl = (size_t)b*Ll + t0 + c2*32 + lane;
                    g_y[bl*DIc + ch0] = acc0;
                    g_y[bl*DIc + ch1] = acc1;
                }
            }
            __syncwarp();
        }
        if (c2 == 0) cur = nxt;
    }

    size_t base0 = ((size_t)(b*NCH + cch)*DIc + ch0)*Sd + s0;
    size_t base1 = ((size_t)(b*NCH + cch)*DIc + ch1)*Sd + s0;
    ull* he0 = (ull*)(g_hend + base0);
    ull* he1 = (ull*)(g_hend + base1);
#pragma unroll
    for (int j = 0; j < 4; j++) { he0[j] = H0[j]; he1[j] = H1[j]; }
}

// K2: sequential chunk combine.
__global__ __launch_bounds__(128) void comb_kernel() {
    int wid = threadIdx.x >> 5, lane = threadIdx.x & 31;
    int wg = blockIdx.x*4 + wid;
    int b = wg / DIc, d = wg % DIc;
    int s0 = lane*8;
    bool powA = (g_powA != 0);
    float av[8];
    if (!powA) {
#pragma unroll
        for (int j = 0; j < 8; j++) av[j] = g_A[(size_t)d*Sd + s0 + j];
    }
    float hin[8] = {};
    for (int c = 0; c < NCH; c++) {
        size_t base = ((size_t)(b*NCH + c)*DIc + d)*Sd + s0;
#pragma unroll
        for (int j = 0; j < 8; j++) g_hin[base + j] = hin[j];
        if (c == NCH-1) break;
        float sd = g_dt[((size_t)(b*Ll + c*LCH + lane))*DIc + d]
                 + g_dt[((size_t)(b*Ll + c*LCH + 32 + lane))*DIc + d];
#pragma unroll
        for (int o = 16; o; o >>= 1) sd += __shfl_xor_sync(0xffffffffu, sd, o);
        const float* he = g_hend + base;
        if (powA) {
            float E  = __expf(-sd);
            float pw = __expf(-sd * (float)(s0 + 1));
#pragma unroll
            for (int j = 0; j < 8; j++) { hin[j] = pw*hin[j] + he[j]; pw *= E; }
        } else {
#pragma unroll
            for (int j = 0; j < 8; j++) hin[j] = __expf(sd*av[j])*hin[j] + he[j];
        }
    }
}

// K3: carry-in correction + D-skip + gating; output rounded to tf32.
__global__ __launch_bounds__(128, 4) void scan2_kernel(const float* __restrict__ Dvec) {
    __shared__ __align__(16) float ring[3][4*256];
    __shared__ float ybuf[4][2][32*17];
    const int tid  = threadIdx.x;
    const int w    = tid >> 5;
    const int lane = tid & 31;
    const int dg   = blockIdx.x % (DIc/8);
    const int cch  = (blockIdx.x / (DIc/8)) % NCH;
    const int b    = blockIdx.x / (NCH*(DIc/8));
    const int ch0  = dg*8 + w*2, ch1 = ch0 + 1;
    const int s0   = lane*8;
    const int t0   = cch*LCH;
    const float nS1 = -(float)(s0 + 1);
    const float* xd = g_xdbl + (size_t)b*Ll*XD;
    float* yb0 = ybuf[w][0];
    float* yb1 = ybuf[w][1];

    const int offc = (tid & 63) * 4;
    const int rw0  = tid >> 6;
    const float* srcC = xd + Rr + Sd + offc;
    unsigned ringaddr[3];
#pragma unroll
    for (int s = 0; s < 3; s++)
        ringaddr[s] = (unsigned)__cvta_generic_to_shared(&ring[s][offc]);

    ull Hi0[4], Hi1[4];
    {
        size_t base0 = ((size_t)(b*NCH + cch)*DIc + ch0)*Sd + s0;
        size_t base1 = ((size_t)(b*NCH + cch)*DIc + ch1)*Sd + s0;
        const ull* h0p = (const ull*)(g_hin + base0);
        const ull* h1p = (const ull*)(g_hin + base1);
#pragma unroll
        for (int j = 0; j < 4; j++) { Hi0[j] = h0p[j]; Hi1[j] = h1p[j]; }
    }

    float a0[8], a1[8];
    bool powA = (g_powA != 0);
    if (!powA) {
#pragma unroll
        for (int j = 0; j < 8; j++) {
            a0[j] = g_A[(size_t)ch0*Sd + s0 + j];
            a1[j] = g_A[(size_t)ch1*Sd + s0 + j];
        }
    }
    float D0 = Dvec[ch0], D1 = Dvec[ch1];

    Chunk cur, nxt;
    load_chunk_k3(b, t0, lane, ch0, ch1, cur);
    load_chunk_k3(b, t0 + 32, lane, ch0, ch1, nxt);

#pragma unroll
    for (int ss = 0; ss < 2; ss++) {
#pragma unroll
        for (int rr = 0; rr < 2; rr++)
            cpa16(ringaddr[ss] + (rw0 + rr*2)*1024,
                  srcC + (size_t)(t0 + ss*4 + rw0 + rr*2)*XD);
        asm volatile("cp.async.commit_group;" ::: "memory");
    }

    float q0 = 1.f, q1 = 1.f, Eq0 = 1.f, Eq1 = 1.f;
    float qv0[8], qv1[8];
    if (!powA) {
#pragma unroll
        for (int j = 0; j < 8; j++) { qv0[j] = 1.f; qv1[j] = 1.f; }
    }
    const unsigned fm = 0xffffffffu;

    for (int c2 = 0; c2 < 2; c2++) {
#pragma unroll
        for (int half = 0; half < 2; half++) {
            for (int q = 0; q < 4; q++) {
                int ss = c2*8 + half*4 + q;
                asm volatile("cp.async.wait_group 1;" ::: "memory");
                __syncthreads();
                int slot = ss % 3;
                const float* rb = ring[slot];
#pragma unroll
                for (int j = 0; j < 4; j++) {
                    ull Cr[4];
                    const float* p = rb + j*256;
                    ulonglong2 c01 = *(const ulonglong2*)(p + s0);
                    ulonglong2 c23 = *(const ulonglong2*)(p + s0 + 4);
                    Cr[0]=c01.x; Cr[1]=c01.y; Cr[2]=c23.x; Cr[3]=c23.y;
                    int ti = half*16 + q*4 + j;
                    float dt0 = __shfl_sync(fm, cur.dt0, ti);
                    float dt1 = __shfl_sync(fm, cur.dt1, ti);
                    float e0  = __shfl_sync(fm, cur.e0,  ti);
                    float e1  = __shfl_sync(fm, cur.e1,  ti);
                    ull Q0[4], Q1[4];
                    if (powA) {
                        q0 *= __expf(dt0 * nS1);  Eq0 *= e0;
                        q1 *= __expf(dt1 * nS1);  Eq1 *= e1;
                        ull E0 = pack2(Eq0*Eq0, Eq0*Eq0);
                        ull E1 = pack2(Eq1*Eq1, Eq1*Eq1);
                        Q0[0] = pack2(q0, q0*Eq0);
                        Q1[0] = pack2(q1, q1*Eq1);
                        Q0[1] = mul2(Q0[0], E0); Q0[2] = mul2(Q0[1], E0); Q0[3] = mul2(Q0[2], E0);
                        Q1[1] = mul2(Q1[0], E1); Q1[2] = mul2(Q1[1], E1); Q1[3] = mul2(Q1[2], E1);
                    } else {
#pragma unroll
                        for (int k = 0; k < 8; k++) {
                            qv0[k] *= __expf(dt0*a0[k]);
                            qv1[k] *= __expf(dt1*a1[k]);
                        }
#pragma unroll
                        for (int k = 0; k < 4; k++) {
                            Q0[k] = pack2(qv0[2*k], qv0[2*k+1]);
                            Q1[k] = pack2(qv1[2*k], qv1[2*k+1]);
                        }
                    }
                    ull ya0 = 0ull, ya1 = 0ull;
#pragma unroll
                    for (int k = 0; k < 4; k++) {
                        ya0 = fma2(mul2(Q0[k], Hi0[k]), Cr[k], ya0);
                        ya1 = fma2(mul2(Q1[k], Hi1[k]), Cr[k], ya1);
                    }
                    float2 u0 = unpack2(ya0);
                    float2 u1 = unpack2(ya1);
                    yb0[lane*17 + q*4 + j] = u0.x + u0.y;
                    yb1[lane*17 + q*4 + j] = u1.x + u1.y;
                }
                int ns = ss + 2;
                if (ns < 16) {
#pragma unroll
                    for (int rr = 0; rr < 2; rr++)
                        cpa16(ringaddr[ns % 3] + (rw0 + rr*2)*1024,
                              srcC + (size_t)(t0 + ns*4 + rw0 + rr*2)*XD);
                }
                asm volatile("cp.async.commit_group;" ::: "memory");
            }
            __syncwarp();
            {
                int t15 = lane & 15;
                int lb  = (lane < 16) ? 0 : 16;
                float acc0 = 0.f, acc1 = 0.f;
#pragma unroll
                for (int l = 0; l < 16; l++) {
                    acc0 += yb0[(lb + l)*17 + t15];
                    acc1 += yb1[(lb + l)*17 + t15];
                }
                acc0 += __shfl_xor_sync(fm, acc0, 16);
                acc1 += __shfl_xor_sync(fm, acc1, 16);
                bool mine = half ? (lane >= 16) : (lane < 16);
                if (mine) {
                    size_t bl = (size_t)b*Ll + t0 + c2*32 + lane;
                    float yl0 = g_y[bl*DIc + ch0];
                    float yl1 = g_y[bl*DIc + ch1];
                    float sg0 = 1.f/(1.f + __expf(-cur.z0));
                    float sg1 = 1.f/(1.f + __expf(-cur.z1));
                    g_y[bl*DIc + ch0] = rndtf((yl0 + acc0 + D0*cur.xa0) * (cur.z0 * sg0));
                    g_y[bl*DIc + ch1] = rndtf((yl1 + acc1 + D1*cur.xa1) * (cur.z1 * sg1));
                }
            }
            __syncwarp();
        }
        if (c2 == 0) cur = nxt;
    }
}

// ---------------- launcher: graph with parallel branches ----------------
extern "C" void kernel_launch(void* const* d_in, const int* in_sizes, int n_in,
                              void* d_out, int out_size) {
    const float* x          = (const float*)d_in[0];
    const float* ln1_g      = (const float*)d_in[1];
    const float* ln1_b      = (const float*)d_in[2];
    const float* ln2_g      = (const float*)d_in[3];
    const float* ln2_b      = (const float*)d_in[4];
    const float* head_w     = (const float*)d_in[5];
    const float* head_b     = (const float*)d_in[6];
    const float* in_proj_w  = (const float*)d_in[7];
    const float* conv_w     = (const float*)d_in[8];
    const float* conv_b     = (const float*)d_in[9];
    const float* x_proj_w   = (const float*)d_in[10];
    const float* dt_proj_w  = (const float*)d_in[11];
    const float* dt_proj_b  = (const float*)d_in[12];
    const float* A_log      = (const float*)d_in[13];
    const float* Dvec       = (const float*)d_in[14];
    const float* out_proj_w = (const float*)d_in[15];
    float* out = (float*)d_out;

    float *u, *uh, *wz, *wxp, *wop, *whd;
    float *xz, *xactr, *yb, *res1, *t2, *part;
    cudaGetSymbolAddress((void**)&u,     g_u);
    cudaGetSymbolAddress((void**)&uh,    g_uh);
    cudaGetSymbolAddress((void**)&wz,    g_wz);
    cudaGetSymbolAddress((void**)&wxp,   g_wxp);
    cudaGetSymbolAddress((void**)&wop,   g_wop);
    cudaGetSymbolAddress((void**)&whd,   g_whd);
    cudaGetSymbolAddress((void**)&xz,    g_xz);
    cudaGetSymbolAddress((void**)&xactr, g_xactr);
    cudaGetSymbolAddress((void**)&yb,    g_y);
    cudaGetSymbolAddress((void**)&res1,  g_res1);
    cudaGetSymbolAddress((void**)&t2,    g_t2);
    cudaGetSymbolAddress((void**)&part,  g_part);

    cudaFuncSetAttribute(tgemm,  cudaFuncAttributeMaxDynamicSharedMemorySize, TG_SMEM);
    cudaFuncSetAttribute(tgemm3, cudaFuncAttributeMaxDynamicSharedMemorySize, T3_SMEM);

    static cudaStream_t s1 = 0, s2 = 0;
    static cudaEvent_t evStart = 0, evPrep = 0, evLn = 0, evZ = 0, evConv = 0, evDt = 0;
    if (!s1) {
        cudaStreamCreateWithFlags(&s1, cudaStreamNonBlocking);
        cudaStreamCreateWithFlags(&s2, cudaStreamNonBlocking);
        cudaEventCreateWithFlags(&evStart, cudaEventDisableTiming);
        cudaEventCreateWithFlags(&evPrep,  cudaEventDisableTiming);
        cudaEventCreateWithFlags(&evLn,    cudaEventDisableTiming);
        cudaEventCreateWithFlags(&evZ,     cudaEventDisableTiming);
        cudaEventCreateWithFlags(&evConv,  cudaEventDisableTiming);
        cudaEventCreateWithFlags(&evDt,    cudaEventDisableTiming);
    }

    // fork: s1 does prep (weights + A) while s0 runs the main chain
    cudaEventRecord(evStart, 0);
    cudaStreamWaitEvent(s1, evStart, 0);
    prep_kernel<<<1024, 256, 0, s1>>>(A_log, in_proj_w, x_proj_w, out_proj_w, head_w);
    cudaEventRecord(evPrep, s1);

    ln1_kernel<<<BL, 128>>>(x, ln1_g, ln1_b, u, uh);
    cudaEventRecord(evLn, 0);

    // s1: z-half GEMM (needs uh + wz; prep already on s1)
    cudaStreamWaitEvent(s1, evLn, 0);
    tgemm<<<dim3(DIc/64, BL/128), 256, TG_SMEM, s1>>>(uh, wz, xz + DIc,
                                                      BL, DIc, Cc, Cc, 2*DIc, 0);
    cudaEventRecord(evZ, s1);

    // s0: x-half 3xTF32 GEMM split-K3 (raw weights, no prep dep) -> add -> conv
    tgemm3<<<dim3(DIc/64, BL/128, 3), 256, T3_SMEM>>>(u, in_proj_w, part,
                                                      128, Cc, DIc, (size_t)BL*DIc);
    addin_kernel<<<(BL*DIc + 255)/256, 256>>>();
    conv_kernel<<<(BL*DIc + 255)/256, 256>>>(conv_w, conv_b);
    cudaEventRecord(evConv, 0);

    // s2: dt projection (exact fp32) in parallel with x_dbl GEMM
    cudaStreamWaitEvent(s2, evConv, 0);
    dt_kernel<<<BL, 192, 0, s2>>>(x_proj_w, dt_proj_w, dt_proj_b);
    cudaEventRecord(evDt, s2);

    // s0: x_dbl split-K4 (needs prep's wxp)
    cudaStreamWaitEvent(0, evPrep, 0);
    tgemm<<<dim3((XD + 63)/64, BL/128, 4), 256, TG_SMEM>>>(xactr, wxp, part,
                                                           BL, XD, 192, DIc, XD, (size_t)BL*XD);
    addx_kernel<<<(BL*XD + 255)/256, 256>>>();

    // join dt, run scans
    cudaStreamWaitEvent(0, evDt, 0);
    scan1_kernel<<<Bb*NCH*(DIc/8), 128>>>();
    comb_kernel<<<Bb*DIc/4, 128>>>();
    cudaStreamWaitEvent(0, evZ, 0);
    scan2_kernel<<<Bb*NCH*(DIc/8), 128>>>(Dvec);

    // out_proj split-K4; ln2 fused with 4-partial add + residual
    tgemm<<<dim3(Cc/64, BL/128, 4), 256, TG_SMEM>>>(yb, wop, part,
                                                    BL, Cc, 192, DIc, Cc, (size_t)BL*Cc);
    ln_add_kernel<<<BL, 128>>>(part, x, ln2_g, ln2_b, res1, t2);

    // head split-K4; final add with bias + residual
    tgemm<<<dim3(Cc/64, BL/128, 4), 256, TG_SMEM>>>(t2, whd, part,
                                                    BL, Cc, 96, Cc, Cc, (size_t)BL*Cc);
    addh_kernel<<<(BL*Cc + 255)/256, 256>>>(head_b, out);
}

// round 15
// speedup vs baseline: 1.0176x; 1.0176x over previous
#include <cuda_runtime.h>
#include <math.h>
#include <stdint.h>

#define Cc  384
#define DIc 768
#define Sd  256
#define Rr  24
#define Kc  4
#define Bb  2
#define Ll  512
#define BL  (Bb*Ll)          // 1024
#define XD  (Rr + 2*Sd)      // 536
#define NCH 8
#define LCH 64

typedef unsigned long long ull;

// ---------------- f32x2 packed helpers ----------------
__device__ __forceinline__ ull fma2(ull a, ull b, ull c) {
    ull d;
    asm("fma.rn.f32x2 %0, %1, %2, %3;" : "=l"(d) : "l"(a), "l"(b), "l"(c));
    return d;
}
__device__ __forceinline__ ull mul2(ull a, ull b) {
    ull d;
    asm("mul.rn.f32x2 %0, %1, %2;" : "=l"(d) : "l"(a), "l"(b));
    return d;
}
__device__ __forceinline__ ull pack2(float x, float y) {
    ull d;
    asm("mov.b64 %0, {%1, %2};" : "=l"(d) : "f"(x), "f"(y));
    return d;
}
__device__ __forceinline__ float2 unpack2(ull v) {
    float2 r;
    asm("mov.b64 {%0, %1}, %2;" : "=f"(r.x), "=f"(r.y) : "l"(v));
    return r;
}

__device__ __forceinline__ void cpa16(uint32_t dst, const void* src) {
    asm volatile("cp.async.ca.shared.global [%0], [%1], 16;" :: "r"(dst), "l"(src));
}
__device__ __forceinline__ uint32_t f2tf(float f) {
    uint32_t r;
    asm("cvt.rna.tf32.f32 %0, %1;" : "=r"(r) : "f"(f));
    return r;
}
__device__ __forceinline__ float rndtf(float f) { return __uint_as_float(f2tf(f)); }

__device__ __forceinline__ void mma8(float* c, const uint32_t* a, const uint32_t* b) {
    asm volatile(
        "mma.sync.aligned.m16n8k8.row.col.f32.tf32.tf32.f32 "
        "{%0,%1,%2,%3}, {%4,%5,%6,%7}, {%8,%9}, {%0,%1,%2,%3};"
        : "+f"(c[0]), "+f"(c[1]), "+f"(c[2]), "+f"(c[3])
        : "r"(a[0]), "r"(a[1]), "r"(a[2]), "r"(a[3]), "r"(b[0]), "r"(b[1]));
}

// ---------------- scratch ----------------
__device__ __align__(16) float g_u[BL*Cc];     // fp32 ln1 output (for tgemm3)
__device__ __align__(16) float g_uh[BL*Cc];    // tf32-rounded ln1 output (for z GEMM)
__device__ __align__(16) float g_wz [DIc*Cc];
__device__ __align__(16) float g_wxp[XD*DIc];
__device__ __align__(16) float g_wop[Cc*DIc];
__device__ __align__(16) float g_whd[Cc*Cc];
__device__ __align__(16) float g_xz[BL*2*DIc];   // z-half used; x-half unused now
__device__ __align__(16) float g_xact[BL*DIc];
__device__ __align__(16) float g_xactr[BL*DIc];
__device__ __align__(16) float g_xdbl[BL*XD];
__device__ __align__(16) float g_dt[BL*DIc];
__device__ __align__(16) float g_e[BL*DIc];
__device__ __align__(16) float g_du[BL*DIc];
__device__ __align__(16) float g_A[DIc*Sd];
__device__ int   g_powA = 1;
__device__ __align__(16) float g_y[BL*DIc];
__device__ __align__(16) float g_res1[BL*Cc];
__device__ __align__(16) float g_t2[BL*Cc];
__device__ __align__(16) float g_part[3*BL*DIc];   // sized for worst user (3x tgemm3)
__device__ __align__(16) float g_hend[Bb*NCH*DIc*Sd];
__device__ __align__(16) float g_hin [Bb*NCH*DIc*Sd];

// ---------------- ln1: fp32 + tf32-rounded outputs ----------------
__global__ __launch_bounds__(128) void ln1_kernel(const float* __restrict__ x,
                                                  const float* __restrict__ gw,
                                                  const float* __restrict__ bw,
                                                  float* __restrict__ u_out,
                                                  float* __restrict__ uh_out) {
    int row = blockIdx.x;
    const float* xr = x + (size_t)row * Cc;
    float v[3];
#pragma unroll
    for (int i = 0; i < 3; i++) v[i] = xr[threadIdx.x + i*128];
    float s = v[0]+v[1]+v[2];
    float q = v[0]*v[0]+v[1]*v[1]+v[2]*v[2];
#pragma unroll
    for (int o = 16; o; o >>= 1) {
        s += __shfl_xor_sync(0xffffffffu, s, o);
        q += __shfl_xor_sync(0xffffffffu, q, o);
    }
    __shared__ float sh[8];
    int wid = threadIdx.x >> 5, ln = threadIdx.x & 31;
    if (ln == 0) { sh[wid] = s; sh[wid+4] = q; }
    __syncthreads();
    s = sh[0]+sh[1]+sh[2]+sh[3];
    q = sh[4]+sh[5]+sh[6]+sh[7];
    float mu  = s * (1.f/Cc);
    float var = q * (1.f/Cc) - mu*mu;
    float rs  = rsqrtf(var + 1e-5f);
#pragma unroll
    for (int i = 0; i < 3; i++) {
        int c = threadIdx.x + i*128;
        float o = (v[i]-mu)*rs*gw[c] + bw[c];
        u_out[(size_t)row*Cc + c]  = o;
        uh_out[(size_t)row*Cc + c] = rndtf(o);
    }
}

// ------------- ln2 fused with 4-partial add; t2 rounded to tf32 -----------------
__global__ __launch_bounds__(128) void ln_add_kernel(const float* __restrict__ qp,
                                                     const float* __restrict__ xr0,
                                                     const float* __restrict__ gw,
                                                     const float* __restrict__ bw,
                                                     float* __restrict__ res_out,
                                                     float* __restrict__ out) {
    int row = blockIdx.x;
    size_t base = (size_t)row * Cc;
    const size_t S = (size_t)BL*Cc;
    float v[3];
#pragma unroll
    for (int i = 0; i < 3; i++) {
        size_t c = base + threadIdx.x + i*128;
        v[i] = (qp[c] + qp[S+c]) + (qp[2*S+c] + qp[3*S+c]) + xr0[c];
        res_out[c] = v[i];
    }
    float s = v[0]+v[1]+v[2];
    float q = v[0]*v[0]+v[1]*v[1]+v[2]*v[2];
#pragma unroll
    for (int o = 16; o; o >>= 1) {
        s += __shfl_xor_sync(0xffffffffu, s, o);
        q += __shfl_xor_sync(0xffffffffu, q, o);
    }
    __shared__ float sh[8];
    int wid = threadIdx.x >> 5, ln = threadIdx.x & 31;
    if (ln == 0) { sh[wid] = s; sh[wid+4] = q; }
    __syncthreads();
    s = sh[0]+sh[1]+sh[2]+sh[3];
    q = sh[4]+sh[5]+sh[6]+sh[7];
    float mu  = s * (1.f/Cc);
    float var = q * (1.f/Cc) - mu*mu;
    float rs  = rsqrtf(var + 1e-5f);
#pragma unroll
    for (int i = 0; i < 3; i++) {
        int c = threadIdx.x + i*128;
        out[base + c] = rndtf((v[i]-mu)*rs*gw[c] + bw[c]);
    }
}

// ------------ 1x tf32 GEMM: 128x64 tile, 256 thr, split-K via gridDim.z ---------
// Operands must be pre-rounded to tf32 (rna); raw-feed is then exact.
#define GP 36
#define ABUF (128*GP)
#define WBUF (64*GP)
#define TG_SMEM ((2*(ABUF+WBUF))*4)   // 55296

__device__ __forceinline__ void tg_stage(const float* __restrict__ A,
                                         const float* __restrict__ W,
                                         int N, int kp, int m0, int n0, int i, int kOff,
                                         uint32_t Au, uint32_t Wu, int tid) {
    int k0 = kOff + (i << 5);
#pragma unroll
    for (int j = 0; j < 4; j++) {
        int idx = tid + j*256;
        int r = idx >> 3, c = idx & 7;
        cpa16(Au + (unsigned)(r*GP + c*4)*4, A + (size_t)(m0+r)*kp + k0 + c*4);
    }
#pragma unroll
    for (int j = 0; j < 2; j++) {
        int idx = tid + j*256;
        int r = idx >> 3, c = idx & 7;
        uint32_t dst = Wu + (unsigned)(r*GP + c*4)*4;
        int gn = n0 + r;
        if (gn < N)
            cpa16(dst, W + (size_t)gn*kp + k0 + c*4);
        else
            asm volatile("st.shared.v4.b32 [%0], {%1,%1,%1,%1};" :: "r"(dst), "r"(0u) : "memory");
    }
    asm volatile("cp.async.commit_group;" ::: "memory");
}

__global__ __launch_bounds__(256) void tgemm(const float* __restrict__ A,
                                             const float* __restrict__ W,
                                             float* __restrict__ out,
                                             int M, int N, int kLen, int kp,
                                             int ldo, size_t pStride) {
    extern __shared__ float sm[];
    uint32_t sb;
    asm("{ .reg .u64 t; cvta.to.shared.u64 t, %1; cvt.u32.u64 %0, t; }" : "=r"(sb) : "l"(sm));
    const int tid = threadIdx.x, lane = tid & 31, wid = tid >> 5;
    const int wm = wid & 3, wn = wid >> 2;
    const int m0 = blockIdx.y * 128, n0 = blockIdx.x * 64;
    const int kOff = blockIdx.z * kLen;
    const int nch = kLen >> 5;
    out += (size_t)blockIdx.z * pStride;

    float* Ab[2] = { sm,        sm + ABUF + WBUF };
    float* Wb[2] = { sm + ABUF, sm + 2*ABUF + WBUF };
    uint32_t Au[2] = { sb,          sb + (ABUF + WBUF)*4 };
    uint32_t Wu[2] = { sb + ABUF*4, sb + (2*ABUF + WBUF)*4 };

    float acc[2][4][4] = {};

    tg_stage(A, W, N, kp, m0, n0, 0, kOff, Au[0], Wu[0], tid);
    if (nch > 1) tg_stage(A, W, N, kp, m0, n0, 1, kOff, Au[1], Wu[1], tid);

    const int lq = lane >> 2, lr = lane & 3;

    for (int i = 0; i < nch; i++) {
        int buf = i & 1;
        if (i + 1 < nch) asm volatile("cp.async.wait_group 1;" ::: "memory");
        else             asm volatile("cp.async.wait_group 0;" ::: "memory");
        __syncthreads();
        const float* Ap = Ab[buf];
        const float* Wp = Wb[buf];
#pragma unroll
        for (int k8 = 0; k8 < 4; k8++) {
            int kb = k8*8 + lr;
            uint32_t ah[2][4];
#pragma unroll
            for (int t = 0; t < 2; t++) {
                int rb = wm*32 + t*16 + lq;
                ah[t][0] = __float_as_uint(Ap[rb*GP + kb]);
                ah[t][1] = __float_as_uint(Ap[(rb+8)*GP + kb]);
                ah[t][2] = __float_as_uint(Ap[rb*GP + kb + 4]);
                ah[t][3] = __float_as_uint(Ap[(rb+8)*GP + kb + 4]);
            }
            uint32_t bh[4][2];
#pragma unroll
            for (int j = 0; j < 4; j++) {
                int nb = wn*32 + j*8 + lq;
                bh[j][0] = __float_as_uint(Wp[nb*GP + kb]);
                bh[j][1] = __float_as_uint(Wp[nb*GP + kb + 4]);
            }
#pragma unroll
            for (int t = 0; t < 2; t++)
#pragma unroll
                for (int j = 0; j < 4; j++)
                    mma8(acc[t][j], ah[t], bh[j]);
        }
        if (i + 2 < nch) {
            __syncthreads();
            tg_stage(A, W, N, kp, m0, n0, i + 2, kOff, Au[buf], Wu[buf], tid);
        }
    }

#pragma unroll
    for (int t = 0; t < 2; t++) {
        int r0 = m0 + wm*32 + t*16 + lq;
#pragma unroll
        for (int j = 0; j < 4; j++) {
            int gn = n0 + wn*32 + j*8 + lr*2;
            if (gn >= N) continue;
            const float* c = acc[t][j];
            float* p0 = out + (size_t)r0 * ldo + gn;
            float* p1 = out + (size_t)(r0+8) * ldo + gn;
            p0[0] = c[0]; p0[1] = c[1];
            p1[0] = c[2]; p1[1] = c[3];
        }
    }
}

// ------- 3x tf32 GEMM (in-loop cvt split), 128x64 tile, K-chunk 16, split-K -----
#define GP3 20
#define A3 (128*GP3)
#define W3 (64*GP3)
#define T3_SMEM ((2*(A3+W3))*4)   // 30720

__device__ __forceinline__ void t3_stage(const float* __restrict__ A,
                                         const float* __restrict__ W,
                                         int kp, int m0, int n0, int i, int kOff,
                                         uint32_t Au, uint32_t Wu, int tid) {
    int k0 = kOff + (i << 4);
#pragma unroll
    for (int j = 0; j < 2; j++) {
        int idx = tid + j*256;
        int r = idx >> 2, c = idx & 3;
        cpa16(Au + (unsigned)(r*GP3 + c*4)*4, A + (size_t)(m0+r)*kp + k0 + c*4);
    }
    {
        int r = tid >> 2, c = tid & 3;
        cpa16(Wu + (unsigned)(r*GP3 + c*4)*4, W + (size_t)(n0+r)*kp + k0 + c*4);
    }
    asm volatile("cp.async.commit_group;" ::: "memory");
}

__global__ __launch_bounds__(256) void tgemm3(const float* __restrict__ A,
                                              const float* __restrict__ W,
                                              float* __restrict__ out,
                                              int kLen, int kp, int ldo, size_t pStride) {
    extern __shared__ float sm[];
    uint32_t sb;
    asm("{ .reg .u64 t; cvta.to.shared.u64 t, %1; cvt.u32.u64 %0, t; }" : "=r"(sb) : "l"(sm));
    const int tid = threadIdx.x, lane = tid & 31, wid = tid >> 5;
    const int wm = wid & 3, wn = wid >> 2;
    const int m0 = blockIdx.y * 128, n0 = blockIdx.x * 64;
    const int kOff = blockIdx.z * kLen;
    const int nch = kLen >> 4;
    out += (size_t)blockIdx.z * pStride;

    float* Ab[2] = { sm,      sm + A3 + W3 };
    float* Wb[2] = { sm + A3, sm + 2*A3 + W3 };
    uint32_t Au[2] = { sb,         sb + (A3 + W3)*4 };
    uint32_t Wu[2] = { sb + A3*4,  sb + (2*A3 + W3)*4 };

    float acc[2][4][4] = {};

    t3_stage(A, W, kp, m0, n0, 0, kOff, Au[0], Wu[0], tid);
    if (nch > 1) t3_stage(A, W, kp, m0, n0, 1, kOff, Au[1], Wu[1], tid);

    const int lq = lane >> 2, lr = lane & 3;

    for (int i = 0; i < nch; i++) {
        int buf = i & 1;
        if (i + 1 < nch) asm volatile("cp.async.wait_group 1;" ::: "memory");
        else             asm volatile("cp.async.wait_group 0;" ::: "memory");
        __syncthreads();
        const float* Ap = Ab[buf];
        const float* Wp = Wb[buf];
#pragma unroll
        for (int k8 = 0; k8 < 2; k8++) {
            int kb = k8*8 + lr;
            uint32_t ah[2][4], al[2][4];
#pragma unroll
            for (int t = 0; t < 2; t++) {
                int rb = wm*32 + t*16 + lq;
                float v0 = Ap[rb*GP3 + kb];
                float v1 = Ap[(rb+8)*GP3 + kb];
                float v2 = Ap[rb*GP3 + kb + 4];
                float v3 = Ap[(rb+8)*GP3 + kb + 4];
                ah[t][0] = f2tf(v0); ah[t][1] = f2tf(v1);
                ah[t][2] = f2tf(v2); ah[t][3] = f2tf(v3);
                al[t][0] = f2tf(v0 - __uint_as_float(ah[t][0]));
                al[t][1] = f2tf(v1 - __uint_as_float(ah[t][1]));
                al[t][2] = f2tf(v2 - __uint_as_float(ah[t][2]));
                al[t][3] = f2tf(v3 - __uint_as_float(ah[t][3]));
            }
            uint32_t bh[4][2], bl[4][2];
#pragma unroll
            for (int j = 0; j < 4; j++) {
                int nb = wn*32 + j*8 + lq;
                float v0 = Wp[nb*GP3 + kb];
                float v1 = Wp[nb*GP3 + kb + 4];
                bh[j][0] = f2tf(v0); bh[j][1] = f2tf(v1);
                bl[j][0] = f2tf(v0 - __uint_as_float(bh[j][0]));
                bl[j][1] = f2tf(v1 - __uint_as_float(bh[j][1]));
            }
#pragma unroll
            for (int t = 0; t < 2; t++)
#pragma unroll
                for (int j = 0; j < 4; j++) {
                    mma8(acc[t][j], ah[t], bh[j]);
                    mma8(acc[t][j], ah[t], bl[j]);
                    mma8(acc[t][j], al[t], bh[j]);
                }
        }
        if (i + 2 < nch) {
            __syncthreads();
            t3_stage(A, W, kp, m0, n0, i + 2, kOff, Au[buf], Wu[buf], tid);
        }
    }

#pragma unroll
    for (int t = 0; t < 2; t++) {
        int r0 = m0 + wm*32 + t*16 + lq;
#pragma unroll
        for (int j = 0; j < 4; j++) {
            int gn = n0 + wn*32 + j*8 + lr*2;
            const float* c = acc[t][j];
            float* p0 = out + (size_t)r0 * ldo + gn;
            float* p1 = out + (size_t)(r0+8) * ldo + gn;
            p0[0] = c[0]; p0[1] = c[1];
            p1[0] = c[2]; p1[1] = c[3];
        }
    }
}

// ---------------- elementwise adds ----------------
__global__ void addx_kernel() {   // 4 partials (pitch 512) -> g_xdbl cols 24..535
    int i = blockIdx.x*256 + threadIdx.x;
    if (i >= BL*512) return;
    const size_t S = (size_t)BL*512;
    int row = i >> 9, col = i & 511;
    g_xdbl[(size_t)row*XD + Rr + col] =
        (g_part[i] + g_part[S+i]) + (g_part[2*S+i] + g_part[3*S+i]);
}
__global__ void addh_kernel(const float* __restrict__ hb, float* __restrict__ out) {
    int i = blockIdx.x*256 + threadIdx.x;
    if (i >= BL*Cc) return;
    const size_t S = (size_t)BL*Cc;
    int col = i - (i/Cc)*Cc;
    out[i] = (g_part[i] + g_part[S+i]) + (g_part[2*S+i] + g_part[3*S+i])
           + g_res1[i] + hb[col];
}

// ------ conv fused with 3-partial in_proj sum: x_act = silu(conv(sum) + b) ------
__global__ void conv_kernel(const float* __restrict__ cw, const float* __restrict__ cb) {
    int i = blockIdx.x * blockDim.x + threadIdx.x;
    if (i >= BL*DIc) return;
    int d  = i % DIc;
    int bl = i / DIc;
    int l  = bl % Ll;
    int b  = bl / Ll;
    const size_t S = (size_t)BL*DIc;
    float acc = cb[d];
#pragma unroll
    for (int k = 0; k < Kc; ++k) {
        int ls = l - (Kc-1) + k;
        if (ls >= 0) {
            size_t idx = (size_t)(b*Ll + ls)*DIc + d;
            float v = g_part[idx] + g_part[S+idx] + g_part[2*S+idx];
            acc += cw[d*Kc + k] * v;
        }
    }
    float sg = 1.f/(1.f + __expf(-acc));
    float xa = acc * sg;
    g_xact[i]  = xa;
    g_xactr[i] = rndtf(xa);
}

// ---------- dt: exact fp32 x_proj dt-slice + dt_proj + softplus + exp/du --------
__global__ __launch_bounds__(192) void dt_kernel(const float* __restrict__ Wx,
                                                 const float* __restrict__ Wdt,
                                                 const float* __restrict__ bdt) {
    __shared__ float sx[DIc];
    __shared__ float sdt[Rr];
    int row = blockIdx.x, tid = threadIdx.x;
    const float* xr = g_xact + (size_t)row * DIc;
    for (int i = tid; i < DIc; i += 192) sx[i] = xr[i];
    __syncthreads();
    int r = tid >> 3, sl = tid & 7;
    const float* wrow = Wx + (size_t)r * DIc;
    float acc = 0.f;
    for (int k = sl; k < DIc; k += 8) acc += sx[k] * wrow[k];
    acc += __shfl_xor_sync(0xffffffffu, acc, 4);
    acc += __shfl_xor_sync(0xffffffffu, acc, 2);
    acc += __shfl_xor_sync(0xffffffffu, acc, 1);
    if (sl == 0) sdt[r] = acc;
    __syncthreads();
    for (int d = tid; d < DIc; d += 192) {
        float a = bdt[d];
#pragma unroll
        for (int rr = 0; rr < Rr; rr++) a += sdt[rr] * Wdt[d*Rr + rr];
        float sp = fmaxf(a, 0.f) + log1pf(__expf(-fabsf(a)));
        size_t idx = (size_t)row*DIc + d;
        g_dt[idx] = sp;
        g_e[idx]  = __expf(-sp);
        g_du[idx] = sp * sx[d];
    }
}

// ------- prep: A precompute/check + weight tf32 roundings ----------
__global__ __launch_bounds__(256) void prep_kernel(const float* __restrict__ Alog,
                                                   const float* __restrict__ Win,
                                                   const float* __restrict__ Wxp,
                                                   const float* __restrict__ Wop,
                                                   const float* __restrict__ Whd) {
    int i0 = blockIdx.x*256 + threadIdx.x;
    int stride = gridDim.x*256;
    for (int i = i0; i < DIc*Sd; i += stride) {
        float a = -__expf(Alog[i]);
        g_A[i] = a;
        float tgt = (float)(i % Sd + 1);
        if (fabsf(a + tgt) > 1e-5f * tgt) g_powA = 0;
    }
    for (int i = i0; i < DIc*Cc; i += stride)
        g_wz[i] = rndtf(Win[(size_t)DIc*Cc + i]);
    for (int i = i0; i < XD*DIc; i += stride) g_wxp[i] = rndtf(Wxp[i]);
    for (int i = i0; i < Cc*DIc; i += stride) g_wop[i] = rndtf(Wop[i]);
    for (int i = i0; i < Cc*Cc;  i += stride) g_whd[i] = rndtf(Whd[i]);
}

// ---------------- chunked selective scan ----------------------------------------
struct Chunk { float dt0, dt1, e0, e1, du0, du1, xa0, xa1, z0, z1; };

__device__ __forceinline__ void load_chunk_k1(int b, int tbase, int lane, int ch0, int ch1, Chunk& c) {
    size_t bl = (size_t)b*Ll + tbase + lane;
    size_t i0 = bl*DIc + ch0, i1 = bl*DIc + ch1;
    c.dt0 = g_dt[i0];  c.dt1 = g_dt[i1];
    c.e0  = g_e[i0];   c.e1  = g_e[i1];
    c.du0 = g_du[i0];  c.du1 = g_du[i1];
}
__device__ __forceinline__ void load_chunk_k3(int b, int tbase, int lane, int ch0, int ch1, Chunk& c) {
    size_t bl = (size_t)b*Ll + tbase + lane;
    size_t i0 = bl*DIc + ch0, i1 = bl*DIc + ch1;
    c.dt0 = g_dt[i0];  c.dt1 = g_dt[i1];
    c.e0  = g_e[i0];   c.e1  = g_e[i1];
    c.xa0 = g_xact[i0]; c.xa1 = g_xact[i1];
    c.z0  = g_xz[bl*(2*DIc) + DIc + ch0];
    c.z1  = g_xz[bl*(2*DIc) + DIc + ch1];
}

struct RowU { ull B[4]; ull C[4]; };

__device__ __forceinline__ void step_update(int ti, int slot, const Chunk& ck, const RowU& r,
                                            ull (&H0)[4], ull (&H1)[4],
                                            bool powA, const float (&a0)[8], const float (&a1)[8],
                                            float nS1, float* yb0, float* yb1, int lane) {
    const unsigned m = 0xffffffffu;
    float dt0 = __shfl_sync(m, ck.dt0, ti);
    float dt1 = __shfl_sync(m, ck.dt1, ti);
    float e0  = __shfl_sync(m, ck.e0,  ti);
    float e1  = __shfl_sync(m, ck.e1,  ti);
    float du0 = __shfl_sync(m, ck.du0, ti);
    float du1 = __shfl_sync(m, ck.du1, ti);
    ull P0[4], P1[4];
    if (powA) {
        float p0 = __expf(dt0 * nS1);
        float p1 = __expf(dt1 * nS1);
        ull E0 = pack2(e0*e0, e0*e0);
        ull E1 = pack2(e1*e1, e1*e1);
        P0[0] = pack2(p0, p0*e0);
        P1[0] = pack2(p1, p1*e1);
        P0[1] = mul2(P0[0], E0); P0[2] = mul2(P0[1], E0); P0[3] = mul2(P0[2], E0);
        P1[1] = mul2(P1[0], E1); P1[2] = mul2(P1[1], E1); P1[3] = mul2(P1[2], E1);
    } else {
#pragma unroll
        for (int j = 0; j < 4; j++) {
            P0[j] = pack2(__expf(dt0*a0[2*j]), __expf(dt0*a0[2*j+1]));
            P1[j] = pack2(__expf(dt1*a1[2*j]), __expf(dt1*a1[2*j+1]));
        }
    }
    ull du0p = pack2(du0, du0);
    ull du1p = pack2(du1, du1);
    ull ya0 = 0ull, ya1 = 0ull;
#pragma unroll
    for (int j = 0; j < 4; j++) {
        H0[j] = fma2(P0[j], H0[j], mul2(du0p, r.B[j]));
        ya0   = fma2(H0[j], r.C[j], ya0);
        H1[j] = fma2(P1[j], H1[j], mul2(du1p, r.B[j]));
        ya1   = fma2(H1[j], r.C[j], ya1);
    }
    float2 u0 = unpack2(ya0);
    float2 u1 = unpack2(ya1);
    yb0[lane*17 + slot] = u0.x + u0.y;
    yb1[lane*17 + slot] = u1.x + u1.y;
}

// K1: local scan per chunk.  grid = Bb*NCH*(DIc/8) = 1536 blocks, 128 thr.
__global__ __launch_bounds__(128, 4) void scan1_kernel() {
    __shared__ __align__(16) float ring[3][4*512];
    __shared__ float ybuf[4][2][32*17];
    const int tid  = threadIdx.x;
    const int w    = tid >> 5;
    const int lane = tid & 31;
    const int dg   = blockIdx.x % (DIc/8);
    const int cch  = (blockIdx.x / (DIc/8)) % NCH;
    const int b    = blockIdx.x / (NCH*(DIc/8));
    const int ch0  = dg*8 + w*2, ch1 = ch0 + 1;
    const int s0   = lane*8;
    const int t0   = cch*LCH;
    const float nS1 = -(float)(s0 + 1);
    const float* xd = g_xdbl + (size_t)b*Ll*XD;
    float* yb0 = ybuf[w][0];
    float* yb1 = ybuf[w][1];

    const int off = tid * 4;
    const float* srcbase = (off < 256) ? (xd + Rr + off) : (xd + Rr + Sd + (off - 256));
    unsigned ringaddr[3];
#pragma unroll
    for (int s = 0; s < 3; s++)
        ringaddr[s] = (unsigned)__cvta_generic_to_shared(&ring[s][off]);

    ull H0[4] = {}, H1[4] = {};
    float a0[8], a1[8];
    bool powA = (g_powA != 0);
    if (!powA) {
#pragma unroll
        for (int j = 0; j < 8; j++) {
            a0[j] = g_A[(size_t)ch0*Sd + s0 + j];
            a1[j] = g_A[(size_t)ch1*Sd + s0 + j];
        }
    } else {
#pragma unroll
        for (int j = 0; j < 8; j++) { a0[j] = 0.f; a1[j] = 0.f; }
    }

    Chunk cur, nxt;
    load_chunk_k1(b, t0, lane, ch0, ch1, cur);
    load_chunk_k1(b, t0 + 32, lane, ch0, ch1, nxt);

#pragma unroll
    for (int ss = 0; ss < 2; ss++) {
        const float* sp = srcbase + (size_t)(t0 + ss*4)*XD;
#pragma unroll
        for (int j = 0; j < 4; j++)
            cpa16(ringaddr[ss] + j*2048, sp + (size_t)j*XD);
        asm volatile("cp.async.commit_group;" ::: "memory");
    }

    for (int c2 = 0; c2 < 2; c2++) {
#pragma unroll
        for (int half = 0; half < 2; half++) {
            for (int q = 0; q < 4; q++) {
                int ss = c2*8 + half*4 + q;
                asm volatile("cp.async.wait_group 1;" ::: "memory");
                __syncthreads();
                int slot = ss % 3;
                const float* rb = ring[slot];
#pragma unroll
                for (int j = 0; j < 4; j++) {
                    RowU r;
                    const float* p = rb + j*512;
                    ulonglong2 b01 = *(const ulonglong2*)(p + s0);
                    ulonglong2 b23 = *(const ulonglong2*)(p + s0 + 4);
                    ulonglong2 c01 = *(const ulonglong2*)(p + 256 + s0);
                    ulonglong2 c23 = *(const ulonglong2*)(p + 256 + s0 + 4);
                    r.B[0]=b01.x; r.B[1]=b01.y; r.B[2]=b23.x; r.B[3]=b23.y;
                    r.C[0]=c01.x; r.C[1]=c01.y; r.C[2]=c23.x; r.C[3]=c23.y;
                    int ti = half*16 + q*4 + j;
                    step_update(ti, q*4 + j, cur, r, H0, H1, powA, a0, a1, nS1, yb0, yb1, lane);
                }
                int ns = ss + 2;
                if (ns < 16) {
                    const float* sp = srcbase + (size_t)(t0 + ns*4)*XD;
#pragma unroll
                    for (int j = 0; j < 4; j++)
                        cpa16(ringaddr[ns % 3] + j*2048, sp + (size_t)j*XD);
                }
                asm volatile("cp.async.commit_group;" ::: "memory");
            }
            __syncwarp();
            {
                int t15 = lane & 15;
                int lb  = (lane < 16) ? 0 : 16;
                float acc0 = 0.f, acc1 = 0.f;
#pragma unroll
                for (int l = 0; l < 16; l++) {
                    acc0 += yb0[(lb + l)*17 + t15];
                    acc1 += yb1[(lb + l)*17 + t15];
                }
                acc0 += __shfl_xor_sync(0xffffffffu, acc0, 16);
                acc1 += __shfl_xor_sync(0xffffffffu, acc1, 16);
                bool mine = half ? (lane >= 16) : (lane < 16);
                if (mine) {
                    size_t bl = (size_t)b*Ll + t0 + c2*32 + lane;
                    g_y[bl*DIc + ch0] = acc0;
                    g_y[bl*DIc + ch1] = acc1;
                }
            }
            __syncwarp();
        }
        if (c2 == 0) cur = nxt;
    }

    size_t base0 = ((size_t)(b*NCH + cch)*DIc + ch0)*Sd + s0;
    size_t base1 = ((size_t)(b*NCH + cch)*DIc + ch1)*Sd + s0;
    ull* he0 = (ull*)(g_hend + base0);
    ull* he1 = (ull*)(g_hend + base1);
#pragma unroll
    for (int j = 0; j < 4; j++) { he0[j] = H0[j]; he1[j] = H1[j]; }
}

// K2: sequential chunk combine.
__global__ __launch_bounds__(128) void comb_kernel() {
    int wid = threadIdx.x >> 5, lane = threadIdx.x & 31;
    int wg = blockIdx.x*4 + wid;
    int b = wg / DIc, d = wg % DIc;
    int s0 = lane*8;
    bool powA = (g_powA != 0);
    float av[8];
    if (!powA) {
#pragma unroll
        for (int j = 0; j < 8; j++) av[j] = g_A[(size_t)d*Sd + s0 + j];
    }
    float hin[8] = {};
    for (int c = 0; c < NCH; c++) {
        size_t base = ((size_t)(b*NCH + c)*DIc + d)*Sd + s0;
#pragma unroll
        for (int j = 0; j < 8; j++) g_hin[base + j] = hin[j];
        if (c == NCH-1) break;
        float sd = g_dt[((size_t)(b*Ll + c*LCH + lane))*DIc + d]
                 + g_dt[((size_t)(b*Ll + c*LCH + 32 + lane))*DIc + d];
#pragma unroll
        for (int o = 16; o; o >>= 1) sd += __shfl_xor_sync(0xffffffffu, sd, o);
        const float* he = g_hend + base;
        if (powA) {
            float E  = __expf(-sd);
            float pw = __expf(-sd * (float)(s0 + 1));
#pragma unroll
            for (int j = 0; j < 8; j++) { hin[j] = pw*hin[j] + he[j]; pw *= E; }
        } else {
#pragma unroll
            for (int j = 0; j < 8; j++) hin[j] = __expf(sd*av[j])*hin[j] + he[j];
        }
    }
}

// K3: carry-in correction + D-skip + gating; output rounded to tf32.
__global__ __launch_bounds__(128, 4) void scan2_kernel(const float* __restrict__ Dvec) {
    __shared__ __align__(16) float ring[3][4*256];
    __shared__ float ybuf[4][2][32*17];
    const int tid  = threadIdx.x;
    const int w    = tid >> 5;
    const int lane = tid & 31;
    const int dg   = blockIdx.x % (DIc/8);
    const int cch  = (blockIdx.x / (DIc/8)) % NCH;
    const int b    = blockIdx.x / (NCH*(DIc/8));
    const int ch0  = dg*8 + w*2, ch1 = ch0 + 1;
    const int s0   = lane*8;
    const int t0   = cch*LCH;
    const float nS1 = -(float)(s0 + 1);
    const float* xd = g_xdbl + (size_t)b*Ll*XD;
    float* yb0 = ybuf[w][0];
    float* yb1 = ybuf[w][1];

    const int offc = (tid & 63) * 4;
    const int rw0  = tid >> 6;
    const float* srcC = xd + Rr + Sd + offc;
    unsigned ringaddr[3];
#pragma unroll
    for (int s = 0; s < 3; s++)
        ringaddr[s] = (unsigned)__cvta_generic_to_shared(&ring[s][offc]);

    ull Hi0[4], Hi1[4];
    {
        size_t base0 = ((size_t)(b*NCH + cch)*DIc + ch0)*Sd + s0;
        size_t base1 = ((size_t)(b*NCH + cch)*DIc + ch1)*Sd + s0;
        const ull* h0p = (const ull*)(g_hin + base0);
        const ull* h1p = (const ull*)(g_hin + base1);
#pragma unroll
        for (int j = 0; j < 4; j++) { Hi0[j] = h0p[j]; Hi1[j] = h1p[j]; }
    }

    float a0[8], a1[8];
    bool powA = (g_powA != 0);
    if (!powA) {
#pragma unroll
        for (int j = 0; j < 8; j++) {
            a0[j] = g_A[(size_t)ch0*Sd + s0 + j];
            a1[j] = g_A[(size_t)ch1*Sd + s0 + j];
        }
    }
    float D0 = Dvec[ch0], D1 = Dvec[ch1];

    Chunk cur, nxt;
    load_chunk_k3(b, t0, lane, ch0, ch1, cur);
    load_chunk_k3(b, t0 + 32, lane, ch0, ch1, nxt);

#pragma unroll
    for (int ss = 0; ss < 2; ss++) {
#pragma unroll
        for (int rr = 0; rr < 2; rr++)
            cpa16(ringaddr[ss] + (rw0 + rr*2)*1024,
                  srcC + (size_t)(t0 + ss*4 + rw0 + rr*2)*XD);
        asm volatile("cp.async.commit_group;" ::: "memory");
    }

    float q0 = 1.f, q1 = 1.f, Eq0 = 1.f, Eq1 = 1.f;
    float qv0[8], qv1[8];
    if (!powA) {
#pragma unroll
        for (int j = 0; j < 8; j++) { qv0[j] = 1.f; qv1[j] = 1.f; }
    }
    const unsigned fm = 0xffffffffu;

    for (int c2 = 0; c2 < 2; c2++) {
#pragma unroll
        for (int half = 0; half < 2; half++) {
            for (int q = 0; q < 4; q++) {
                int ss = c2*8 + half*4 + q;
                asm volatile("cp.async.wait_group 1;" ::: "memory");
                __syncthreads();
                int slot = ss % 3;
                const float* rb = ring[slot];
#pragma unroll
                for (int j = 0; j < 4; j++) {
                    ull Cr[4];
                    const float* p = rb + j*256;
                    ulonglong2 c01 = *(const ulonglong2*)(p + s0);
                    ulonglong2 c23 = *(const ulonglong2*)(p + s0 + 4);
                    Cr[0]=c01.x; Cr[1]=c01.y; Cr[2]=c23.x; Cr[3]=c23.y;
                    int ti = half*16 + q*4 + j;
                    float dt0 = __shfl_sync(fm, cur.dt0, ti);
                    float dt1 = __shfl_sync(fm, cur.dt1, ti);
                    float e0  = __shfl_sync(fm, cur.e0,  ti);
                    float e1  = __shfl_sync(fm, cur.e1,  ti);
                    ull Q0[4], Q1[4];
                    if (powA) {
                        q0 *= __expf(dt0 * nS1);  Eq0 *= e0;
                        q1 *= __expf(dt1 * nS1);  Eq1 *= e1;
                        ull E0 = pack2(Eq0*Eq0, Eq0*Eq0);
                        ull E1 = pack2(Eq1*Eq1, Eq1*Eq1);
                        Q0[0] = pack2(q0, q0*Eq0);
                        Q1[0] = pack2(q1, q1*Eq1);
                        Q0[1] = mul2(Q0[0], E0); Q0[2] = mul2(Q0[1], E0); Q0[3] = mul2(Q0[2], E0);
                        Q1[1] = mul2(Q1[0], E1); Q1[2] = mul2(Q1[1], E1); Q1[3] = mul2(Q1[2], E1);
                    } else {
#pragma unroll
                        for (int k = 0; k < 8; k++) {
                            qv0[k] *= __expf(dt0*a0[k]);
                            qv1[k] *= __expf(dt1*a1[k]);
                        }
#pragma unroll
                        for (int k = 0; k < 4; k++) {
                            Q0[k] = pack2(qv0[2*k], qv0[2*k+1]);
                            Q1[k] = pack2(qv1[2*k], qv1[2*k+1]);
                        }
                    }
                    ull ya0 = 0ull, ya1 = 0ull;
#pragma unroll
                    for (int k = 0; k < 4; k++) {
                        ya0 = fma2(mul2(Q0[k], Hi0[k]), Cr[k], ya0);
                        ya1 = fma2(mul2(Q1[k], Hi1[k]), Cr[k], ya1);
                    }
                    float2 u0 = unpack2(ya0);
                    float2 u1 = unpack2(ya1);
                    yb0[lane*17 + q*4 + j] = u0.x + u0.y;
                    yb1[lane*17 + q*4 + j] = u1.x + u1.y;
                }
                int ns = ss + 2;
                if (ns < 16) {
#pragma unroll
                    for (int rr = 0; rr < 2; rr++)
                        cpa16(ringaddr[ns % 3] + (rw0 + rr*2)*1024,
                              srcC + (size_t)(t0 + ns*4 + rw0 + rr*2)*XD);
                }
                asm volatile("cp.async.commit_group;" ::: "memory");
            }
            __syncwarp();
            {
                int t15 = lane & 15;
                int lb  = (lane < 16) ? 0 : 16;
                float acc0 = 0.f, acc1 = 0.f;
#pragma unroll
                for (int l = 0; l < 16; l++) {
                    acc0 += yb0[(lb + l)*17 + t15];
                    acc1 += yb1[(lb + l)*17 + t15];
                }
                acc0 += __shfl_xor_sync(fm, acc0, 16);
                acc1 += __shfl_xor_sync(fm, acc1, 16);
                bool mine = half ? (lane >= 16) : (lane < 16);
                if (mine) {
                    size_t bl = (size_t)b*Ll + t0 + c2*32 + lane;
                    float yl0 = g_y[bl*DIc + ch0];
                    float yl1 = g_y[bl*DIc + ch1];
                    float sg0 = 1.f/(1.f + __expf(-cur.z0));
                    float sg1 = 1.f/(1.f + __expf(-cur.z1));
                    g_y[bl*DIc + ch0] = rndtf((yl0 + acc0 + D0*cur.xa0) * (cur.z0 * sg0));
                    g_y[bl*DIc + ch1] = rndtf((yl1 + acc1 + D1*cur.xa1) * (cur.z1 * sg1));
                }
            }
            __syncwarp();
        }
        if (c2 == 0) cur = nxt;
    }
}

// ---------------- launcher: graph with parallel branches ----------------
extern "C" void kernel_launch(void* const* d_in, const int* in_sizes, int n_in,
                              void* d_out, int out_size) {
    const float* x          = (const float*)d_in[0];
    const float* ln1_g      = (const float*)d_in[1];
    const float* ln1_b      = (const float*)d_in[2];
    const float* ln2_g      = (const float*)d_in[3];
    const float* ln2_b      = (const float*)d_in[4];
    const float* head_w     = (const float*)d_in[5];
    const float* head_b     = (const float*)d_in[6];
    const float* in_proj_w  = (const float*)d_in[7];
    const float* conv_w     = (const float*)d_in[8];
    const float* conv_b     = (const float*)d_in[9];
    const float* x_proj_w   = (const float*)d_in[10];
    const float* dt_proj_w  = (const float*)d_in[11];
    const float* dt_proj_b  = (const float*)d_in[12];
    const float* A_log      = (const float*)d_in[13];
    const float* Dvec       = (const float*)d_in[14];
    const float* out_proj_w = (const float*)d_in[15];
    float* out = (float*)d_out;

    float *u, *uh, *wz, *wxp, *wop, *whd;
    float *xz, *xactr, *yb, *res1, *t2, *part;
    cudaGetSymbolAddress((void**)&u,     g_u);
    cudaGetSymbolAddress((void**)&uh,    g_uh);
    cudaGetSymbolAddress((void**)&wz,    g_wz);
    cudaGetSymbolAddress((void**)&wxp,   g_wxp);
    cudaGetSymbolAddress((void**)&wop,   g_wop);
    cudaGetSymbolAddress((void**)&whd,   g_whd);
    cudaGetSymbolAddress((void**)&xz,    g_xz);
    cudaGetSymbolAddress((void**)&xactr, g_xactr);
    cudaGetSymbolAddress((void**)&yb,    g_y);
    cudaGetSymbolAddress((void**)&res1,  g_res1);
    cudaGetSymbolAddress((void**)&t2,    g_t2);
    cudaGetSymbolAddress((void**)&part,  g_part);

    cudaFuncSetAttribute(tgemm,  cudaFuncAttributeMaxDynamicSharedMemorySize, TG_SMEM);
    cudaFuncSetAttribute(tgemm3, cudaFuncAttributeMaxDynamicSharedMemorySize, T3_SMEM);

    static cudaStream_t s1 = 0, s2 = 0;
    static cudaEvent_t evStart = 0, evPrep = 0, evLn = 0, evZ = 0, evConv = 0, evDt = 0;
    if (!s1) {
        cudaStreamCreateWithFlags(&s1, cudaStreamNonBlocking);
        cudaStreamCreateWithFlags(&s2, cudaStreamNonBlocking);
        cudaEventCreateWithFlags(&evStart, cudaEventDisableTiming);
        cudaEventCreateWithFlags(&evPrep,  cudaEventDisableTiming);
        cudaEventCreateWithFlags(&evLn,    cudaEventDisableTiming);
        cudaEventCreateWithFlags(&evZ,     cudaEventDisableTiming);
        cudaEventCreateWithFlags(&evConv,  cudaEventDisableTiming);
        cudaEventCreateWithFlags(&evDt,    cudaEventDisableTiming);
    }

    // fork: s1 does prep (weights + A) while s0 runs the main chain
    cudaEventRecord(evStart, 0);
    cudaStreamWaitEvent(s1, evStart, 0);
    prep_kernel<<<1024, 256, 0, s1>>>(A_log, in_proj_w, x_proj_w, out_proj_w, head_w);
    cudaEventRecord(evPrep, s1);

    ln1_kernel<<<BL, 128>>>(x, ln1_g, ln1_b, u, uh);
    cudaEventRecord(evLn, 0);

    // s1: z-half GEMM (needs uh + wz; prep already on s1)
    cudaStreamWaitEvent(s1, evLn, 0);
    tgemm<<<dim3(DIc/64, BL/128), 256, TG_SMEM, s1>>>(uh, wz, xz + DIc,
                                                      BL, DIc, Cc, Cc, 2*DIc, 0);
    cudaEventRecord(evZ, s1);

    // s0: x-half 3xTF32 GEMM split-K3 -> conv (fused 3-partial sum)
    tgemm3<<<dim3(DIc/64, BL/128, 3), 256, T3_SMEM>>>(u, in_proj_w, part,
                                                      128, Cc, DIc, (size_t)BL*DIc);
    conv_kernel<<<(BL*DIc + 255)/256, 256>>>(conv_w, conv_b);
    cudaEventRecord(evConv, 0);

    // s2: dt projection (exact fp32) in parallel with x_dbl GEMM
    cudaStreamWaitEvent(s2, evConv, 0);
    dt_kernel<<<BL, 192, 0, s2>>>(x_proj_w, dt_proj_w, dt_proj_b);
    cudaEventRecord(evDt, s2);

    // s0: x_dbl (B/C only, N=512) split-K4 (needs prep's wxp)
    cudaStreamWaitEvent(0, evPrep, 0);
    tgemm<<<dim3(8, BL/128, 4), 256, TG_SMEM>>>(xactr, wxp + (size_t)Rr*DIc, part,
                                                BL, 512, 192, DIc, 512, (size_t)BL*512);
    addx_kernel<<<(BL*512 + 255)/256, 256>>>();

    // join dt, run scans
    cudaStreamWaitEvent(0, evDt, 0);
    scan1_kernel<<<Bb*NCH*(DIc/8), 128>>>();
    comb_kernel<<<Bb*DIc/4, 128>>>();
    cudaStreamWaitEvent(0, evZ, 0);
    scan2_kernel<<<Bb*NCH*(DIc/8), 128>>>(Dvec);

    // out_proj split-K4; ln2 fused with 4-partial add + residual
    tgemm<<<dim3(Cc/64, BL/128, 4), 256, TG_SMEM>>>(yb, wop, part,
                                                    BL, Cc, 192, DIc, Cc, (size_t)BL*Cc);
    ln_add_kernel<<<BL, 128>>>(part, x, ln2_g, ln2_b, res1, t2);

    // head split-K4; final add with bias + residual
    tgemm<<<dim3(Cc/64, BL/128, 4), 256, TG_SMEM>>>(t2, whd, part,
                                                    BL, Cc, 96, Cc, Cc, (size_t)BL*Cc);
    addh_kernel<<<(BL*Cc + 255)/256, 256>>>(head_b, out);
}